// round 2
// baseline (speedup 1.0000x reference)
#include <cuda_runtime.h>
#include <math.h>

// ---------------- problem dims ----------------
#define N_NODES   15
#define N_EDGES   120
#define D1        480          // 15*32
#define D2        1920         // 15*128
#define EMBED     2048
#define D3        30720        // 15*2048
#define F1        1024
#define F2        512

// ---------------- scratch (device globals; no allocs allowed) ----------------
__device__ float g_h1[D1];
__device__ float g_h2[D2];          // PRE-relu accumulator (bias-initialized)
__device__ float g_h3[D3];          // bias-initialized accumulator
__device__ float g_A[N_NODES * N_NODES];
__device__ float g_hW1[N_NODES * F1];
__device__ float g_x1[N_NODES * F1];
__device__ float g_hW2[N_NODES * F2];
__device__ float g_x2[N_NODES * F2];
__device__ float g_mean[F2];
__device__ float g_ctxpre[F2];

// ---------------- init: reset accumulators every replay ----------------
__global__ void k_init(const float* __restrict__ b2, const float* __restrict__ b3) {
    int idx = blockIdx.x * 256 + threadIdx.x;
    if (idx < D3)              g_h3[idx] = b3[idx];
    if (idx < D2)              g_h2[idx] = b2[idx];
    if (idx < N_NODES * F1)    g_hW1[idx] = 0.f;
    if (idx < N_NODES * F2)    g_hW2[idx] = 0.f;
    if (idx < F2)              g_ctxpre[idx] = 0.f;
}

// ---------------- normalized adjacency (A + I with sym deg norm) ----------------
__global__ void k_adj(const int* __restrict__ edge_index) {
    __shared__ float sA[N_NODES * N_NODES];
    __shared__ float sdeg[N_NODES];
    __shared__ float sdinv[N_NODES];
    int t = threadIdx.x;
    if (t < N_NODES * N_NODES) sA[t] = 0.f;
    if (t < N_NODES) sdeg[t] = 1.0f;                 // self loop
    __syncthreads();
    const int* src = edge_index;
    const int* dst = edge_index + N_EDGES;
    for (int e = t; e < N_EDGES; e += blockDim.x)
        atomicAdd(&sdeg[dst[e]], 1.0f);
    __syncthreads();
    if (t < N_NODES) sdinv[t] = rsqrtf(sdeg[t]);
    __syncthreads();
    for (int e = t; e < N_EDGES; e += blockDim.x) {
        int s = src[e], d = dst[e];
        atomicAdd(&sA[d * N_NODES + s], sdinv[s] * sdinv[d]);
    }
    if (t < N_NODES)
        atomicAdd(&sA[t * N_NODES + t], sdinv[t] * sdinv[t]);
    __syncthreads();
    if (t < N_NODES * N_NODES) g_A[t] = sA[t];
}

// ---------------- MLP layer 1: [15] -> [480], relu ----------------
__global__ void k_h1(const float* __restrict__ f, const float* __restrict__ W1,
                     const float* __restrict__ b1) {
    __shared__ float sf[N_NODES];
    int t = threadIdx.x;
    if (t < N_NODES) sf[t] = f[t];
    __syncthreads();
    for (int j = t; j < D1; j += blockDim.x) {
        float s = b1[j];
#pragma unroll
        for (int k = 0; k < N_NODES; ++k) s += sf[k] * W1[k * D1 + j];
        g_h1[j] = fmaxf(s, 0.f);
    }
}

// ---------------- MLP layer 2: [480] -> [1920] (pre-relu, atomic k-split) ----------------
// grid = dim3(15, 4), block = 128.  KCH = 120.
__global__ void k_h2(const float* __restrict__ W2) {
    __shared__ float sh[120];
    int t = threadIdx.x;
    int k0 = blockIdx.y * 120;
    if (t < 120) sh[t] = g_h1[k0 + t];
    __syncthreads();
    int j = blockIdx.x * 128 + t;
    float s = 0.f;
#pragma unroll 8
    for (int kk = 0; kk < 120; ++kk)
        s += sh[kk] * W2[(k0 + kk) * D2 + j];
    atomicAdd(&g_h2[j], s);
}

// ---------------- Big GEMV: relu(h2) @ W3 -> h3[30720]  (236 MB stream) ----------------
// grid = dim3(30, 16), block = 256.  Each thread: float4 of 4 outputs, 120 k's.
__global__ void k_h3(const float* __restrict__ W3) {
    __shared__ float sh[120];
    int t = threadIdx.x;
    int k0 = blockIdx.y * 120;
    if (t < 120) sh[t] = fmaxf(g_h2[k0 + t], 0.f);    // fused relu
    __syncthreads();
    int jv = blockIdx.x * 256 + t;                    // float4 index within row
    const float4* Wv = reinterpret_cast<const float4*>(W3);
    float ax = 0.f, ay = 0.f, az = 0.f, aw = 0.f;
#pragma unroll 8
    for (int kk = 0; kk < 120; ++kk) {
        float4 w = Wv[(size_t)(k0 + kk) * (D3 / 4) + jv];
        float h = sh[kk];
        ax += h * w.x; ay += h * w.y; az += h * w.z; aw += h * w.w;
    }
    int j = jv * 4;
    atomicAdd(&g_h3[j + 0], ax);
    atomicAdd(&g_h3[j + 1], ay);
    atomicAdd(&g_h3[j + 2], az);
    atomicAdd(&g_h3[j + 3], aw);
}

// ---------------- GCN1 GEMM: h3[15,2048] @ gW1[2048,1024] (atomic k-split) ----------------
// grid = dim3(8, 16), block = 128. KCH = 128.
__global__ void k_g1(const float* __restrict__ gW1) {
    __shared__ float sh[N_NODES][128];
    int t = threadIdx.x;
    int k0 = blockIdx.y * 128;
    for (int p = t; p < N_NODES * 128; p += 128) {
        int i = p >> 7, kk = p & 127;
        sh[i][kk] = g_h3[i * EMBED + k0 + kk];
    }
    __syncthreads();
    int j = blockIdx.x * 128 + t;
    float acc[N_NODES];
#pragma unroll
    for (int i = 0; i < N_NODES; ++i) acc[i] = 0.f;
    for (int kk = 0; kk < 128; ++kk) {
        float w = gW1[(k0 + kk) * F1 + j];
#pragma unroll
        for (int i = 0; i < N_NODES; ++i) acc[i] += sh[i][kk] * w;
    }
#pragma unroll
    for (int i = 0; i < N_NODES; ++i)
        atomicAdd(&g_hW1[i * F1 + j], acc[i]);
}

// ---------------- GCN1 aggregate: x1 = relu(A @ hW1 + gb1) ----------------
// grid = 8, block = 128
__global__ void k_agg1(const float* __restrict__ gb1) {
    __shared__ float sA[N_NODES * N_NODES];
    int t = threadIdx.x;
    for (int p = t; p < N_NODES * N_NODES; p += 128) sA[p] = g_A[p];
    __syncthreads();
    int j = blockIdx.x * 128 + t;
    float hv[N_NODES];
#pragma unroll
    for (int s = 0; s < N_NODES; ++s) hv[s] = g_hW1[s * F1 + j];
    float bb = gb1[j];
#pragma unroll
    for (int i = 0; i < N_NODES; ++i) {
        float a = bb;
#pragma unroll
        for (int s = 0; s < N_NODES; ++s) a += sA[i * N_NODES + s] * hv[s];
        g_x1[i * F1 + j] = fmaxf(a, 0.f);
    }
}

// ---------------- GCN2 GEMM: x1[15,1024] @ gW2[1024,512] ----------------
// grid = dim3(4, 8), block = 128. KCH = 128.
__global__ void k_g2(const float* __restrict__ gW2) {
    __shared__ float sh[N_NODES][128];
    int t = threadIdx.x;
    int k0 = blockIdx.y * 128;
    for (int p = t; p < N_NODES * 128; p += 128) {
        int i = p >> 7, kk = p & 127;
        sh[i][kk] = g_x1[i * F1 + k0 + kk];
    }
    __syncthreads();
    int j = blockIdx.x * 128 + t;
    float acc[N_NODES];
#pragma unroll
    for (int i = 0; i < N_NODES; ++i) acc[i] = 0.f;
    for (int kk = 0; kk < 128; ++kk) {
        float w = gW2[(k0 + kk) * F2 + j];
#pragma unroll
        for (int i = 0; i < N_NODES; ++i) acc[i] += sh[i][kk] * w;
    }
#pragma unroll
    for (int i = 0; i < N_NODES; ++i)
        atomicAdd(&g_hW2[i * F2 + j], acc[i]);
}

// ---------------- GCN2 aggregate: x2 = A @ hW2 + gb2 ; also mean over nodes ----------------
// grid = 4, block = 128
__global__ void k_agg2(const float* __restrict__ gb2) {
    __shared__ float sA[N_NODES * N_NODES];
    int t = threadIdx.x;
    for (int p = t; p < N_NODES * N_NODES; p += 128) sA[p] = g_A[p];
    __syncthreads();
    int j = blockIdx.x * 128 + t;
    float hv[N_NODES];
#pragma unroll
    for (int s = 0; s < N_NODES; ++s) hv[s] = g_hW2[s * F2 + j];
    float bb = gb2[j];
    float m = 0.f;
#pragma unroll
    for (int i = 0; i < N_NODES; ++i) {
        float a = bb;
#pragma unroll
        for (int s = 0; s < N_NODES; ++s) a += sA[i * N_NODES + s] * hv[s];
        g_x2[i * F2 + j] = a;
        m += a;
    }
    g_mean[j] = m * (1.0f / N_NODES);
}

// ---------------- ctx GEMV: ctxpre = mean_x @ attW (atomic k-split) ----------------
// grid = dim3(4, 8), block = 128. KCH = 64.
__global__ void k_ctx(const float* __restrict__ attW) {
    __shared__ float sm[64];
    int t = threadIdx.x;
    int k0 = blockIdx.y * 64;
    if (t < 64) sm[t] = g_mean[k0 + t];
    __syncthreads();
    int j = blockIdx.x * 128 + t;
    float s = 0.f;
#pragma unroll 8
    for (int kk = 0; kk < 64; ++kk)
        s += sm[kk] * attW[(k0 + kk) * F2 + j];
    atomicAdd(&g_ctxpre[j], s);
}

// ---------------- tail: scores, rep, logits, softmax/loss ----------------
// 1 block, 512 threads
__global__ void k_tail(const float* __restrict__ fcW, const float* __restrict__ fcb,
                       const float* __restrict__ target, float* __restrict__ out) {
    __shared__ float sctx[F2];
    __shared__ float sx[N_NODES * F2];
    __shared__ float srep[F2];
    __shared__ float sscores[N_NODES];
    __shared__ float slog[3];
    int t = threadIdx.x;
    int w = t >> 5, l = t & 31;

    sctx[t] = tanhf(g_ctxpre[t]);
    for (int p = t; p < N_NODES * F2; p += 512) sx[p] = g_x2[p];
    __syncthreads();

    // scores[i] = sigmoid(x2[i] . ctx)   (one warp per node)
    if (w < N_NODES) {
        float p = 0.f;
        for (int j = l; j < F2; j += 32) p += sx[w * F2 + j] * sctx[j];
#pragma unroll
        for (int o = 16; o; o >>= 1) p += __shfl_down_sync(0xffffffffu, p, o);
        if (l == 0) sscores[w] = 1.0f / (1.0f + expf(-p));
    }
    __syncthreads();

    // rep[j] = sum_i x2[i][j] * scores[i]
    {
        float r = 0.f;
#pragma unroll
        for (int i = 0; i < N_NODES; ++i) r += sx[i * F2 + t] * sscores[i];
        srep[t] = r;
    }
    __syncthreads();

    // logits[c] = rep . fcW[:,c] + fcb[c]   (one warp per class)
    if (w < 3) {
        float p = 0.f;
        for (int j = l; j < F2; j += 32) p += srep[j] * fcW[j * 3 + w];
#pragma unroll
        for (int o = 16; o; o >>= 1) p += __shfl_down_sync(0xffffffffu, p, o);
        if (l == 0) slog[w] = p + fcb[w];
    }
    __syncthreads();

    if (t == 0) {
        // cls = argmax(target)
        int cls = 0;
        float tb = target[0];
        if (target[1] > tb) { tb = target[1]; cls = 1; }
        if (target[2] > tb) { tb = target[2]; cls = 2; }
        float m = fmaxf(slog[0], fmaxf(slog[1], slog[2]));
        float e0 = expf(slog[0] - m), e1 = expf(slog[1] - m), e2 = expf(slog[2] - m);
        float se = e0 + e1 + e2;
        float lse = m + logf(se);
        out[0] = -(slog[cls] - lse);
        out[1] = e0 / se;
        out[2] = e1 / se;
        out[3] = e2 / se;
    }
}

// ---------------- launcher ----------------
extern "C" void kernel_launch(void* const* d_in, const int* in_sizes, int n_in,
                              void* d_out, int out_size) {
    const float* features = (const float*)d_in[0];
    const int*   edges    = (const int*)  d_in[1];
    const float* target   = (const float*)d_in[2];
    const float* W1  = (const float*)d_in[3];
    const float* b1  = (const float*)d_in[4];
    const float* W2  = (const float*)d_in[5];
    const float* b2  = (const float*)d_in[6];
    const float* W3  = (const float*)d_in[7];
    const float* b3  = (const float*)d_in[8];
    const float* gW1 = (const float*)d_in[9];
    const float* gb1 = (const float*)d_in[10];
    const float* gW2 = (const float*)d_in[11];
    const float* gb2 = (const float*)d_in[12];
    const float* attW = (const float*)d_in[13];
    const float* fcW  = (const float*)d_in[14];
    const float* fcb  = (const float*)d_in[15];
    float* out = (float*)d_out;

    k_init<<<(D3 + 255) / 256, 256>>>(b2, b3);
    k_adj<<<1, 256>>>(edges);
    k_h1<<<1, 128>>>(features, W1, b1);
    k_h2<<<dim3(15, 4), 128>>>(W2);
    k_h3<<<dim3(30, 16), 256>>>(W3);
    k_g1<<<dim3(8, 16), 128>>>(gW1);
    k_agg1<<<8, 128>>>(gb1);
    k_g2<<<dim3(4, 8), 128>>>(gW2);
    k_agg2<<<4, 128>>>(gb2);
    k_ctx<<<dim3(4, 8), 128>>>(attW);
    k_tail<<<1, 512>>>(fcW, fcb, target, out);
}

// round 5
// speedup vs baseline: 1.6337x; 1.6337x over previous
#include <cuda_runtime.h>
#include <math.h>

#define N_NODES   15
#define N_EDGES   120
#define D1        480          // 15*32
#define D2        1920         // 15*128
#define EMBED     2048
#define D3        30720        // 15*2048
#define F1        1024
#define F2        512

#define NB        140
#define NT        768
#define TH        (NB * NT)    // 107520 = 7680 * 14

// ---------------- scratch ----------------
__device__ float g_h1[D1];
__device__ float g_h2[D2];                 // pre-relu accumulator (bias-init)
__device__ float g_h3[D3];                 // bias-init accumulator [15][2048]
__device__ float g_A[N_NODES * N_NODES];
__device__ float g_hW1[N_NODES * F1];
__device__ float g_x1[N_NODES * F1];
__device__ float g_hW2[N_NODES * F2];
__device__ float g_x2[N_NODES * F2];
__device__ float g_mean[F2];
__device__ float g_ctxpre[F2];

// ---------------- grid barrier (generation-based, replay-safe) ----------------
__device__ unsigned g_cnt = 0;
__device__ unsigned g_gen = 0;

__device__ __forceinline__ void grid_sync() {
    __syncthreads();
    if (threadIdx.x == 0) {
        unsigned gen = *(volatile unsigned*)&g_gen;
        __threadfence();
        if (atomicAdd(&g_cnt, 1u) == NB - 1) {
            g_cnt = 0;
            __threadfence();
            atomicAdd(&g_gen, 1u);
        } else {
            while (*(volatile unsigned*)&g_gen == gen) { }
        }
        __threadfence();
    }
    __syncthreads();
}

// ---------------- fused persistent kernel ----------------
__global__ __launch_bounds__(NT, 1)
void fused_gnn(const float* __restrict__ features,
               const int*   __restrict__ edges,
               const float* __restrict__ target,
               const float* __restrict__ W1,  const float* __restrict__ b1,
               const float* __restrict__ W2,  const float* __restrict__ b2,
               const float* __restrict__ W3,  const float* __restrict__ b3,
               const float* __restrict__ gW1, const float* __restrict__ gb1,
               const float* __restrict__ gW2, const float* __restrict__ gb2,
               const float* __restrict__ attW,
               const float* __restrict__ fcW, const float* __restrict__ fcb,
               float* __restrict__ out)
{
    __shared__ float sA[N_NODES * N_NODES];
    __shared__ float sdeg[N_NODES];
    __shared__ float sx[N_NODES * F2];
    __shared__ float sctx[F2];
    __shared__ float srep[F2];
    __shared__ float sscores[N_NODES];
    __shared__ float slog[3];

    const int t = threadIdx.x;
    const int b = blockIdx.x;
    const int g = b * NT + t;

    // ======== Phase A: init accumulators + adjacency + MLP layer 1 ========
    for (int idx = g; idx < D3; idx += TH)              g_h3[idx] = b3[idx];
    for (int idx = g; idx < D2; idx += TH)              g_h2[idx] = b2[idx];
    for (int idx = g; idx < N_NODES * F1; idx += TH)    g_hW1[idx] = 0.f;
    for (int idx = g; idx < N_NODES * F2; idx += TH)    g_hW2[idx] = 0.f;
    for (int idx = g; idx < F2; idx += TH)              g_ctxpre[idx] = 0.f;

    if (b == 0) {
        // normalized adjacency (A + I, sym deg norm), block 0 only
        const int* src = edges;
        const int* dst = edges + N_EDGES;
        if (t < N_NODES * N_NODES) sA[t] = 0.f;
        if (t < N_NODES) sdeg[t] = 1.0f;                // self loop
        __syncthreads();
        if (t < N_EDGES) atomicAdd(&sdeg[dst[t]], 1.0f);
        __syncthreads();
        if (t < N_NODES) sdeg[t] = rsqrtf(sdeg[t]);     // now deg^-1/2
        __syncthreads();
        if (t < N_EDGES) {
            int s = src[t], d = dst[t];
            atomicAdd(&sA[d * N_NODES + s], sdeg[s] * sdeg[d]);
        }
        if (t < N_NODES) atomicAdd(&sA[t * N_NODES + t], sdeg[t] * sdeg[t]);
        __syncthreads();
        if (t < N_NODES * N_NODES) g_A[t] = sA[t];
    }
    if (b == 1) {
        // h1 = relu(f @ W1 + b1), 480 outputs
        if (t < D1) {
            float s = __ldg(&b1[t]);
#pragma unroll
            for (int k = 0; k < N_NODES; ++k)
                s += __ldg(&features[k]) * __ldg(&W1[k * D1 + t]);
            g_h1[t] = fmaxf(s, 0.f);
        }
    }
    grid_sync();

    // ======== Phase B: h2 += h1 @ W2   (1920 j x 32 k-chunks of 15) ========
    if (g < D2 * 32) {
        int j  = g % D2;
        int k0 = (g / D2) * 15;
        float s = 0.f;
#pragma unroll
        for (int kk = 0; kk < 15; ++kk)
            s += __ldcg(&g_h1[k0 + kk]) * __ldg(&W2[(k0 + kk) * D2 + j]);
        atomicAdd(&g_h2[j], s);
    }
    grid_sync();

    // ======== Phase C: h3 += relu(h2) @ W3  (236 MB stream) ========
    // 7680 float4 columns x 14 k-slices; one float4 column per thread.
    {
        const float4* Wv = reinterpret_cast<const float4*>(W3);
        int jv = g % 7680;
        int sl = g / 7680;                  // 0..13
        float ax = 0.f, ay = 0.f, az = 0.f, aw = 0.f;
#pragma unroll 4
        for (int k = sl; k < D2; k += 14) {
            float h = fmaxf(__ldcg(&g_h2[k]), 0.f);
            float4 w = __ldg(&Wv[(size_t)k * 7680 + jv]);
            ax += h * w.x; ay += h * w.y; az += h * w.z; aw += h * w.w;
        }
        int jj = jv * 4;
        atomicAdd(&g_h3[jj + 0], ax);
        atomicAdd(&g_h3[jj + 1], ay);
        atomicAdd(&g_h3[jj + 2], az);
        atomicAdd(&g_h3[jj + 3], aw);
    }
    grid_sync();

    // ======== Phase D: hW1 += h3[15,2048] @ gW1[2048,1024] ========
    // 512 float2-cols x 64 k-chunks of 32
    if (g < 512 * 64) {
        int j2 = g & 511;
        int k0 = (g >> 9) * 32;
        float2 acc[N_NODES];
#pragma unroll
        for (int i = 0; i < N_NODES; ++i) { acc[i].x = 0.f; acc[i].y = 0.f; }
        const float2* Wv = reinterpret_cast<const float2*>(gW1);
#pragma unroll 4
        for (int kk = 0; kk < 32; ++kk) {
            int k = k0 + kk;
            float2 w = __ldg(&Wv[(k << 9) + j2]);
#pragma unroll
            for (int i = 0; i < N_NODES; ++i) {
                float h = __ldcg(&g_h3[i * EMBED + k]);
                acc[i].x += h * w.x; acc[i].y += h * w.y;
            }
        }
        int j = j2 * 2;
#pragma unroll
        for (int i = 0; i < N_NODES; ++i) {
            atomicAdd(&g_hW1[i * F1 + j],     acc[i].x);
            atomicAdd(&g_hW1[i * F1 + j + 1], acc[i].y);
        }
    }
    grid_sync();

    // ======== Phase E: x1 = relu(A @ hW1 + gb1) ========
    if (b < 2) {
        for (int p = t; p < N_NODES * N_NODES; p += NT) sA[p] = __ldcg(&g_A[p]);
        __syncthreads();
        int j = b * NT + t;
        if (j < F1) {
            float hv[N_NODES];
#pragma unroll
            for (int s = 0; s < N_NODES; ++s) hv[s] = __ldcg(&g_hW1[s * F1 + j]);
            float bb = __ldg(&gb1[j]);
#pragma unroll
            for (int i = 0; i < N_NODES; ++i) {
                float a = bb;
#pragma unroll
                for (int s = 0; s < N_NODES; ++s) a += sA[i * N_NODES + s] * hv[s];
                g_x1[i * F1 + j] = fmaxf(a, 0.f);
            }
        }
    }
    grid_sync();

    // ======== Phase F: hW2 += x1[15,1024] @ gW2[1024,512] ========
    // 256 float2-cols x 32 k-chunks of 32
    if (g < 256 * 32) {
        int j2 = g & 255;
        int k0 = (g >> 8) * 32;
        float2 acc[N_NODES];
#pragma unroll
        for (int i = 0; i < N_NODES; ++i) { acc[i].x = 0.f; acc[i].y = 0.f; }
        const float2* Wv = reinterpret_cast<const float2*>(gW2);
#pragma unroll 4
        for (int kk = 0; kk < 32; ++kk) {
            int k = k0 + kk;
            float2 w = __ldg(&Wv[(k << 8) + j2]);
#pragma unroll
            for (int i = 0; i < N_NODES; ++i) {
                float h = __ldcg(&g_x1[i * F1 + k]);
                acc[i].x += h * w.x; acc[i].y += h * w.y;
            }
        }
        int j = j2 * 2;
#pragma unroll
        for (int i = 0; i < N_NODES; ++i) {
            atomicAdd(&g_hW2[i * F2 + j],     acc[i].x);
            atomicAdd(&g_hW2[i * F2 + j + 1], acc[i].y);
        }
    }
    grid_sync();

    // ======== Phase G: x2 = A @ hW2 + gb2 ; mean over nodes ========
    if (b == 0) {
        for (int p = t; p < N_NODES * N_NODES; p += NT) sA[p] = __ldcg(&g_A[p]);
        __syncthreads();
        if (t < F2) {
            int j = t;
            float hv[N_NODES];
#pragma unroll
            for (int s = 0; s < N_NODES; ++s) hv[s] = __ldcg(&g_hW2[s * F2 + j]);
            float bb = __ldg(&gb2[j]);
            float m = 0.f;
#pragma unroll
            for (int i = 0; i < N_NODES; ++i) {
                float a = bb;
#pragma unroll
                for (int s = 0; s < N_NODES; ++s) a += sA[i * N_NODES + s] * hv[s];
                g_x2[i * F2 + j] = a;
                m += a;
            }
            g_mean[j] = m * (1.0f / N_NODES);
        }
    }
    grid_sync();

    // ======== Phase H: ctxpre += mean @ attW  (512 j x 16 k-chunks of 32) ========
    if (g < F2 * 16) {
        int j  = g & 511;
        int k0 = (g >> 9) * 32;
        float s = 0.f;
#pragma unroll 8
        for (int kk = 0; kk < 32; ++kk)
            s += __ldcg(&g_mean[k0 + kk]) * __ldg(&attW[(k0 + kk) * F2 + j]);
        atomicAdd(&g_ctxpre[j], s);
    }
    grid_sync();

    // ======== Phase I: tail (block 0 only) ========
    if (b == 0) {
        int w = t >> 5, l = t & 31;
        if (t < F2) sctx[t] = tanhf(__ldcg(&g_ctxpre[t]));
        for (int p = t; p < N_NODES * F2; p += NT) sx[p] = __ldcg(&g_x2[p]);
        __syncthreads();

        if (w < N_NODES) {
            float p = 0.f;
            for (int j = l; j < F2; j += 32) p += sx[w * F2 + j] * sctx[j];
#pragma unroll
            for (int o = 16; o; o >>= 1) p += __shfl_down_sync(0xffffffffu, p, o);
            if (l == 0) sscores[w] = 1.0f / (1.0f + expf(-p));
        }
        __syncthreads();

        if (t < F2) {
            float r = 0.f;
#pragma unroll
            for (int i = 0; i < N_NODES; ++i) r += sx[i * F2 + t] * sscores[i];
            srep[t] = r;
        }
        __syncthreads();

        if (w < 3) {
            float p = 0.f;
            for (int j = l; j < F2; j += 32) p += srep[j] * __ldg(&fcW[j * 3 + w]);
#pragma unroll
            for (int o = 16; o; o >>= 1) p += __shfl_down_sync(0xffffffffu, p, o);
            if (l == 0) slog[w] = p + __ldg(&fcb[w]);
        }
        __syncthreads();

        if (t == 0) {
            int cls = 0;
            float tb = __ldg(&target[0]);
            float t1 = __ldg(&target[1]), t2 = __ldg(&target[2]);
            if (t1 > tb) { tb = t1; cls = 1; }
            if (t2 > tb) { tb = t2; cls = 2; }
            float m = fmaxf(slog[0], fmaxf(slog[1], slog[2]));
            float e0 = expf(slog[0] - m), e1 = expf(slog[1] - m), e2 = expf(slog[2] - m);
            float se = e0 + e1 + e2;
            float lse = m + logf(se);
            out[0] = -(slog[cls] - lse);
            out[1] = e0 / se;
            out[2] = e1 / se;
            out[3] = e2 / se;
        }
    }
}

// ---------------- launcher ----------------
extern "C" void kernel_launch(void* const* d_in, const int* in_sizes, int n_in,
                              void* d_out, int out_size) {
    const float* features = (const float*)d_in[0];
    const int*   edges    = (const int*)  d_in[1];
    const float* target   = (const float*)d_in[2];
    const float* W1   = (const float*)d_in[3];
    const float* b1   = (const float*)d_in[4];
    const float* W2   = (const float*)d_in[5];
    const float* b2   = (const float*)d_in[6];
    const float* W3   = (const float*)d_in[7];
    const float* b3   = (const float*)d_in[8];
    const float* gW1  = (const float*)d_in[9];
    const float* gb1  = (const float*)d_in[10];
    const float* gW2  = (const float*)d_in[11];
    const float* gb2  = (const float*)d_in[12];
    const float* attW = (const float*)d_in[13];
    const float* fcW  = (const float*)d_in[14];
    const float* fcb  = (const float*)d_in[15];
    float* out = (float*)d_out;

    fused_gnn<<<NB, NT>>>(features, edges, target, W1, b1, W2, b2, W3, b3,
                          gW1, gb1, gW2, gb2, attW, fcW, fcb, out);
}

// round 6
// speedup vs baseline: 2.2715x; 1.3904x over previous
#include <cuda_runtime.h>
#include <math.h>

#define N_NODES   15
#define N_EDGES   120
#define D1        480          // 15*32
#define D2        1920         // 15*128
#define EMBED     2048
#define D3        30720        // 15*2048
#define F1        1024
#define F2        512

#define NB        140
#define NT        768
#define TH        (NB * NT)    // 107520 = 7680 * 14

// ---------------- scratch ----------------
__device__ float g_h1[D1];
__device__ float g_h2[D2];                 // pre-relu accumulator (bias-init)
__device__ float g_h3[D3];                 // bias-init accumulator [15][2048]
__device__ float g_A[N_NODES * N_NODES];
__device__ float g_hW1[N_NODES * F1];
__device__ float g_x1[N_NODES * F1];
__device__ float g_hW2[N_NODES * F2];
__device__ float g_x2[N_NODES * F2];
__device__ float g_mean[F2];
__device__ float g_ctxpre[F2];

// ---------------- grid barrier (generation-based, replay-safe) ----------------
__device__ unsigned g_cnt = 0;
__device__ unsigned g_gen = 0;

__device__ __forceinline__ void grid_sync() {
    __syncthreads();
    if (threadIdx.x == 0) {
        unsigned gen = *(volatile unsigned*)&g_gen;
        __threadfence();
        if (atomicAdd(&g_cnt, 1u) == NB - 1) {
            g_cnt = 0;
            __threadfence();
            atomicAdd(&g_gen, 1u);
        } else {
            while (*(volatile unsigned*)&g_gen == gen) { }
        }
        __threadfence();
    }
    __syncthreads();
}

// ---------------- fused persistent kernel ----------------
__global__ __launch_bounds__(NT, 1)
void fused_gnn(const float* __restrict__ features,
               const int*   __restrict__ edges,
               const float* __restrict__ target,
               const float* __restrict__ W1,  const float* __restrict__ b1,
               const float* __restrict__ W2,  const float* __restrict__ b2,
               const float* __restrict__ W3,  const float* __restrict__ b3,
               const float* __restrict__ gW1, const float* __restrict__ gb1,
               const float* __restrict__ gW2, const float* __restrict__ gb2,
               const float* __restrict__ attW,
               const float* __restrict__ fcW, const float* __restrict__ fcb,
               float* __restrict__ out)
{
    __shared__ float sbuf[N_NODES * F2];   // 7680 floats, reused per phase
    __shared__ float sA[N_NODES * N_NODES];
    __shared__ float sdeg[N_NODES];
    __shared__ float sctx[F2];
    __shared__ float srep[F2];
    __shared__ float sscores[N_NODES];
    __shared__ float slog[3];

    const int t = threadIdx.x;
    const int b = blockIdx.x;
    const int g = b * NT + t;

    // ======== Phase A: init accumulators + adjacency + MLP layer 1 ========
    for (int idx = g; idx < D3; idx += TH)              g_h3[idx] = b3[idx];
    for (int idx = g; idx < D2; idx += TH)              g_h2[idx] = b2[idx];
    for (int idx = g; idx < N_NODES * F1; idx += TH)    g_hW1[idx] = 0.f;
    for (int idx = g; idx < N_NODES * F2; idx += TH)    g_hW2[idx] = 0.f;
    for (int idx = g; idx < F2; idx += TH)              g_ctxpre[idx] = 0.f;

    if (b == 0) {
        const int* src = edges;
        const int* dst = edges + N_EDGES;
        if (t < N_NODES * N_NODES) sA[t] = 0.f;
        if (t < N_NODES) sdeg[t] = 1.0f;                // self loop
        __syncthreads();
        if (t < N_EDGES) atomicAdd(&sdeg[dst[t]], 1.0f);
        __syncthreads();
        if (t < N_NODES) sdeg[t] = rsqrtf(sdeg[t]);     // deg^-1/2
        __syncthreads();
        if (t < N_EDGES) {
            int s = src[t], d = dst[t];
            atomicAdd(&sA[d * N_NODES + s], sdeg[s] * sdeg[d]);
        }
        if (t < N_NODES) atomicAdd(&sA[t * N_NODES + t], sdeg[t] * sdeg[t]);
        __syncthreads();
        if (t < N_NODES * N_NODES) g_A[t] = sA[t];
    }
    if (b == 1) {
        // h1 = relu(f @ W1 + b1)
        if (t < D1) {
            float s = __ldg(&b1[t]);
#pragma unroll
            for (int k = 0; k < N_NODES; ++k)
                s += __ldg(&features[k]) * __ldg(&W1[k * D1 + t]);
            g_h1[t] = fmaxf(s, 0.f);
        }
    }
    grid_sync();

    // ======== Phase B: h2 += h1 @ W2  (1920 j x 32 k-chunks of 15) ========
    {
        if (t < D1) sbuf[t] = __ldcg(&g_h1[t]);
        __syncthreads();
        if (g < D2 * 32) {
            int j  = g % D2;
            int k0 = (g / D2) * 15;
            float s = 0.f;
#pragma unroll
            for (int kk = 0; kk < 15; ++kk)
                s += sbuf[k0 + kk] * __ldg(&W2[(k0 + kk) * D2 + j]);
            atomicAdd(&g_h2[j], s);
        }
    }
    grid_sync();

    // ======== Phase C: h3 += relu(h2) @ W3  (236 MB stream) ========
    {
        for (int p = t; p < D2; p += NT)
            sbuf[p] = fmaxf(__ldcg(&g_h2[p]), 0.f);      // fused relu, staged
        __syncthreads();

        const float4* Wv = reinterpret_cast<const float4*>(W3);
        int jv = g % 7680;
        int sl = g / 7680;                  // 0..13
        float ax = 0.f, ay = 0.f, az = 0.f, aw = 0.f;
#pragma unroll 8
        for (int k = sl; k < D2; k += 14) {
            float h = sbuf[k];
            float4 w = __ldg(&Wv[(size_t)k * 7680 + jv]);
            ax += h * w.x; ay += h * w.y; az += h * w.z; aw += h * w.w;
        }
        int jj = jv * 4;
        atomicAdd(&g_h3[jj + 0], ax);
        atomicAdd(&g_h3[jj + 1], ay);
        atomicAdd(&g_h3[jj + 2], az);
        atomicAdd(&g_h3[jj + 3], aw);
    }
    grid_sync();

    // ======== Phase D: hW1 += h3[15,2048] @ gW1[2048,1024] ========
    // 128 tiles: kc = b>>1 (64 chunks of 32), jh = b&1 (two 256-wide float2 halves)
    if (b < 128) {
        int kc = b >> 1, jh = b & 1;
        if (t < N_NODES * 32) {
            int i = t >> 5, kk = t & 31;
            sbuf[t] = __ldcg(&g_h3[i * EMBED + kc * 32 + kk]);
        }
        __syncthreads();
        if (t < 256) {
            int j2 = jh * 256 + t;
            const float2* Wv = reinterpret_cast<const float2*>(gW1);
            float2 acc[N_NODES];
#pragma unroll
            for (int i = 0; i < N_NODES; ++i) { acc[i].x = 0.f; acc[i].y = 0.f; }
#pragma unroll 8
            for (int kk = 0; kk < 32; ++kk) {
                float2 w = __ldg(&Wv[((kc * 32 + kk) << 9) + j2]);
#pragma unroll
                for (int i = 0; i < N_NODES; ++i) {
                    float h = sbuf[(i << 5) + kk];
                    acc[i].x += h * w.x; acc[i].y += h * w.y;
                }
            }
            int j = j2 * 2;
#pragma unroll
            for (int i = 0; i < N_NODES; ++i) {
                atomicAdd(&g_hW1[i * F1 + j],     acc[i].x);
                atomicAdd(&g_hW1[i * F1 + j + 1], acc[i].y);
            }
        }
    }
    grid_sync();

    // ======== Phase E: x1 = relu(A @ hW1 + gb1) ========
    if (b < 2) {
        for (int p = t; p < N_NODES * N_NODES; p += NT) sA[p] = __ldcg(&g_A[p]);
        __syncthreads();
        int j = b * NT + t;
        if (j < F1) {
            float hv[N_NODES];
#pragma unroll
            for (int s = 0; s < N_NODES; ++s) hv[s] = __ldcg(&g_hW1[s * F1 + j]);
            float bb = __ldg(&gb1[j]);
#pragma unroll
            for (int i = 0; i < N_NODES; ++i) {
                float a = bb;
#pragma unroll
                for (int s = 0; s < N_NODES; ++s) a += sA[i * N_NODES + s] * hv[s];
                g_x1[i * F1 + j] = fmaxf(a, 0.f);
            }
        }
    }
    grid_sync();

    // ======== Phase F: hW2 += x1[15,1024] @ gW2[1024,512] ========
    // 64 tiles: kc = b>>1 (32 chunks of 32), jh = b&1 (two 128-wide float2 halves)
    if (b < 64) {
        int kc = b >> 1, jh = b & 1;
        if (t < N_NODES * 32) {
            int i = t >> 5, kk = t & 31;
            sbuf[t] = __ldcg(&g_x1[i * F1 + kc * 32 + kk]);
        }
        __syncthreads();
        if (t < 128) {
            int j2 = jh * 128 + t;
            const float2* Wv = reinterpret_cast<const float2*>(gW2);
            float2 acc[N_NODES];
#pragma unroll
            for (int i = 0; i < N_NODES; ++i) { acc[i].x = 0.f; acc[i].y = 0.f; }
#pragma unroll 8
            for (int kk = 0; kk < 32; ++kk) {
                float2 w = __ldg(&Wv[((kc * 32 + kk) << 8) + j2]);
#pragma unroll
                for (int i = 0; i < N_NODES; ++i) {
                    float h = sbuf[(i << 5) + kk];
                    acc[i].x += h * w.x; acc[i].y += h * w.y;
                }
            }
            int j = j2 * 2;
#pragma unroll
            for (int i = 0; i < N_NODES; ++i) {
                atomicAdd(&g_hW2[i * F2 + j],     acc[i].x);
                atomicAdd(&g_hW2[i * F2 + j + 1], acc[i].y);
            }
        }
    }
    grid_sync();

    // ======== Phase G: x2 = A @ hW2 + gb2 ; mean over nodes ========
    if (b == 0) {
        for (int p = t; p < N_NODES * N_NODES; p += NT) sA[p] = __ldcg(&g_A[p]);
        __syncthreads();
        if (t < F2) {
            int j = t;
            float hv[N_NODES];
#pragma unroll
            for (int s = 0; s < N_NODES; ++s) hv[s] = __ldcg(&g_hW2[s * F2 + j]);
            float bb = __ldg(&gb2[j]);
            float m = 0.f;
#pragma unroll
            for (int i = 0; i < N_NODES; ++i) {
                float a = bb;
#pragma unroll
                for (int s = 0; s < N_NODES; ++s) a += sA[i * N_NODES + s] * hv[s];
                g_x2[i * F2 + j] = a;
                m += a;
            }
            g_mean[j] = m * (1.0f / N_NODES);
        }
    }
    grid_sync();

    // ======== Phase H: ctxpre += mean @ attW  (16 k-chunks of 32) ========
    if (b < 16) {
        if (t < 32) sbuf[t] = __ldcg(&g_mean[b * 32 + t]);
        __syncthreads();
        if (t < F2) {
            int k0 = b * 32;
            float s = 0.f;
#pragma unroll 8
            for (int kk = 0; kk < 32; ++kk)
                s += sbuf[kk] * __ldg(&attW[(k0 + kk) * F2 + t]);
            atomicAdd(&g_ctxpre[t], s);
        }
    }
    grid_sync();

    // ======== Phase I: tail (block 0 only) ========
    if (b == 0) {
        int w = t >> 5, l = t & 31;
        if (t < F2) sctx[t] = tanhf(__ldcg(&g_ctxpre[t]));
        for (int p = t; p < N_NODES * F2; p += NT) sbuf[p] = __ldcg(&g_x2[p]);
        __syncthreads();

        if (w < N_NODES) {
            float p = 0.f;
            for (int j = l; j < F2; j += 32) p += sbuf[w * F2 + j] * sctx[j];
#pragma unroll
            for (int o = 16; o; o >>= 1) p += __shfl_down_sync(0xffffffffu, p, o);
            if (l == 0) sscores[w] = 1.0f / (1.0f + expf(-p));
        }
        __syncthreads();

        if (t < F2) {
            float r = 0.f;
#pragma unroll
            for (int i = 0; i < N_NODES; ++i) r += sbuf[i * F2 + t] * sscores[i];
            srep[t] = r;
        }
        __syncthreads();

        if (w < 3) {
            float p = 0.f;
            for (int j = l; j < F2; j += 32) p += srep[j] * __ldg(&fcW[j * 3 + w]);
#pragma unroll
            for (int o = 16; o; o >>= 1) p += __shfl_down_sync(0xffffffffu, p, o);
            if (l == 0) slog[w] = p + __ldg(&fcb[w]);
        }
        __syncthreads();

        if (t == 0) {
            int cls = 0;
            float tb = __ldg(&target[0]);
            float t1 = __ldg(&target[1]), t2 = __ldg(&target[2]);
            if (t1 > tb) { tb = t1; cls = 1; }
            if (t2 > tb) { tb = t2; cls = 2; }
            float m = fmaxf(slog[0], fmaxf(slog[1], slog[2]));
            float e0 = expf(slog[0] - m), e1 = expf(slog[1] - m), e2 = expf(slog[2] - m);
            float se = e0 + e1 + e2;
            float lse = m + logf(se);
            out[0] = -(slog[cls] - lse);
            out[1] = e0 / se;
            out[2] = e1 / se;
            out[3] = e2 / se;
        }
    }
}

// ---------------- launcher ----------------
extern "C" void kernel_launch(void* const* d_in, const int* in_sizes, int n_in,
                              void* d_out, int out_size) {
    const float* features = (const float*)d_in[0];
    const int*   edges    = (const int*)  d_in[1];
    const float* target   = (const float*)d_in[2];
    const float* W1   = (const float*)d_in[3];
    const float* b1   = (const float*)d_in[4];
    const float* W2   = (const float*)d_in[5];
    const float* b2   = (const float*)d_in[6];
    const float* W3   = (const float*)d_in[7];
    const float* b3   = (const float*)d_in[8];
    const float* gW1  = (const float*)d_in[9];
    const float* gb1  = (const float*)d_in[10];
    const float* gW2  = (const float*)d_in[11];
    const float* gb2  = (const float*)d_in[12];
    const float* attW = (const float*)d_in[13];
    const float* fcW  = (const float*)d_in[14];
    const float* fcb  = (const float*)d_in[15];
    float* out = (float*)d_out;

    fused_gnn<<<NB, NT>>>(features, edges, target, W1, b1, W2, b2, W3, b3,
                          gW1, gb1, gW2, gb2, attW, fcW, fcb, out);
}

// round 11
// speedup vs baseline: 2.5844x; 1.1377x over previous
#include <cuda_runtime.h>
#include <math.h>

#define N_NODES   15
#define N_EDGES   120
#define D1        480          // 15*32
#define D2        1920         // 15*128
#define EMBED     2048
#define D3        30720        // 15*2048
#define F1        1024
#define F2        512

#define NB        140
#define NT        768
#define TH        (NB * NT)    // 107520 = 7680 * 14

// ---------------- scratch (zero-init at load; every replay re-zeroes accumulators) ----------------
__device__ float g_h2[D2];                 // accumulator (bias added at consume)
__device__ float g_h3[D3];                 // accumulator (bias added at consume)
__device__ float g_A[N_NODES * N_NODES];
__device__ float g_hW1[N_NODES * F1];      // accumulator
__device__ float g_x1[N_NODES * F1];
__device__ float g_hW2[N_NODES * F2];      // accumulator
__device__ float g_x2[N_NODES * F2];
__device__ float g_mean[F2];
__device__ float g_ctxpre[F2];             // accumulator

// ---------------- grid barrier (generation-based, replay-safe) ----------------
__device__ unsigned g_cnt = 0;
__device__ unsigned g_gen = 0;

__device__ __forceinline__ void grid_sync() {
    __syncthreads();
    if (threadIdx.x == 0) {
        unsigned gen = *(volatile unsigned*)&g_gen;
        __threadfence();
        if (atomicAdd(&g_cnt, 1u) == NB - 1) {
            g_cnt = 0;
            __threadfence();
            atomicAdd(&g_gen, 1u);
        } else {
            while (*(volatile unsigned*)&g_gen == gen) { }
        }
        __threadfence();
    }
    __syncthreads();
}

// ---------------- fused persistent kernel ----------------
__global__ __launch_bounds__(NT, 1)
void fused_gnn(const float* __restrict__ features,
               const int*   __restrict__ edges,
               const float* __restrict__ target,
               const float* __restrict__ W1,  const float* __restrict__ b1,
               const float* __restrict__ W2,  const float* __restrict__ b2,
               const float* __restrict__ W3,  const float* __restrict__ b3,
               const float* __restrict__ gW1, const float* __restrict__ gb1,
               const float* __restrict__ gW2, const float* __restrict__ gb2,
               const float* __restrict__ attW,
               const float* __restrict__ fcW, const float* __restrict__ fcb,
               float* __restrict__ out)
{
    __shared__ float sbuf[N_NODES * F2];   // 7680 floats, reused per phase
    __shared__ float sA[N_NODES * N_NODES];
    __shared__ float sdeg[N_NODES];
    __shared__ float sctx[F2];
    __shared__ float srep[F2];
    __shared__ float sscores[N_NODES];
    __shared__ float slog[3];

    const int t = threadIdx.x;
    const int b = blockIdx.x;
    const int g = b * NT + t;

    // ======== Phase A': adjacency (block 139) + h1 (per-block smem) + h2 accumulation ========
    if (b == 139) {
        const int* src = edges;
        const int* dst = edges + N_EDGES;
        if (t < N_NODES * N_NODES) sA[t] = 0.f;
        if (t < N_NODES) sdeg[t] = 1.0f;                // self loop
        __syncthreads();
        if (t < N_EDGES) atomicAdd(&sdeg[dst[t]], 1.0f);
        __syncthreads();
        if (t < N_NODES) sdeg[t] = rsqrtf(sdeg[t]);     // deg^-1/2
        __syncthreads();
        if (t < N_EDGES) {
            int s = src[t], d = dst[t];
            atomicAdd(&sA[d * N_NODES + s], sdeg[s] * sdeg[d]);
        }
        if (t < N_NODES) atomicAdd(&sA[t * N_NODES + t], sdeg[t] * sdeg[t]);
        __syncthreads();
        if (t < N_NODES * N_NODES) g_A[t] = sA[t];
    } else if (b < 120) {
        // h1 = relu(f @ W1 + b1) computed redundantly in smem (W1 L2-hot after 1st block)
        if (t < D1) {
            float s = __ldg(&b1[t]);
#pragma unroll
            for (int k = 0; k < N_NODES; ++k)
                s += __ldg(&features[k]) * __ldg(&W1[k * D1 + t]);
            sbuf[t] = fmaxf(s, 0.f);
        }
        __syncthreads();
        // h2 += h1 @ W2 : 1920 j x 48 k-chunks of 10 (92160 tasks = 120 blocks)
        int j = g % D2;
        int k0 = (g / D2) * 10;
        float s = 0.f;
#pragma unroll
        for (int kk = 0; kk < 10; ++kk)
            s += sbuf[k0 + kk] * __ldcs(&W2[(k0 + kk) * D2 + j]);
        atomicAdd(&g_h2[j], s);
    }
    grid_sync();

    // ======== Phase C: h3 += relu(h2 + b2) @ W3  (236 MB stream) ========
    {
        for (int p = t; p < D2; p += NT)
            sbuf[p] = fmaxf(__ldcg(&g_h2[p]) + __ldg(&b2[p]), 0.f);
        __syncthreads();

        const float4* Wv = reinterpret_cast<const float4*>(W3);
        int jv = g % 7680;
        int sl = g / 7680;                  // 0..13
        float ax = 0.f, ay = 0.f, az = 0.f, aw = 0.f;
#pragma unroll 8
        for (int k = sl; k < D2; k += 14) {
            float h = sbuf[k];
            float4 w = __ldcs(&Wv[(size_t)k * 7680 + jv]);
            ax += h * w.x; ay += h * w.y; az += h * w.z; aw += h * w.w;
        }
        int jj = jv * 4;
        atomicAdd(&g_h3[jj + 0], ax);
        atomicAdd(&g_h3[jj + 1], ay);
        atomicAdd(&g_h3[jj + 2], az);
        atomicAdd(&g_h3[jj + 3], aw);
    }
    grid_sync();

    // ======== Phase D: hW1 += (h3+b3)[15,2048] @ gW1[2048,1024] ========
    // 128 blocks, k-chunk 16, 512 j2 threads each.  Idle blocks zero h2.
    if (b < 128) {
        int k0 = b * 16;
        if (t < N_NODES * 16) {
            int i = t >> 4, kk = t & 15;
            int idx = i * EMBED + k0 + kk;
            sbuf[t] = __ldcg(&g_h3[idx]) + __ldg(&b3[idx]);
        }
        __syncthreads();
        if (t < 512) {
            const float2* Wv = reinterpret_cast<const float2*>(gW1);
            float2 acc[N_NODES];
#pragma unroll
            for (int i = 0; i < N_NODES; ++i) { acc[i].x = 0.f; acc[i].y = 0.f; }
#pragma unroll
            for (int kk = 0; kk < 16; ++kk) {
                float2 w = __ldcs(&Wv[((k0 + kk) << 9) + t]);
#pragma unroll
                for (int i = 0; i < N_NODES; ++i) {
                    float h = sbuf[(i << 4) + kk];
                    acc[i].x += h * w.x; acc[i].y += h * w.y;
                }
            }
            int j = t * 2;
#pragma unroll
            for (int i = 0; i < N_NODES; ++i) {
                atomicAdd(&g_hW1[i * F1 + j],     acc[i].x);
                atomicAdd(&g_hW1[i * F1 + j + 1], acc[i].y);
            }
        }
    } else {
        int idx = (b - 128) * NT + t;
        if (idx < D2) g_h2[idx] = 0.f;                 // re-zero for next replay
    }
    grid_sync();

    // ======== Phase E: x1 = relu(A @ hW1 + gb1)  (16 blocks x 64 j) ========
    if (b < 16) {
        if (t < N_NODES * N_NODES) sA[t] = __ldcg(&g_A[t]);
        __syncthreads();
        if (t < 64) {
            int j = b * 64 + t;
            float hv[N_NODES];
#pragma unroll
            for (int s = 0; s < N_NODES; ++s) hv[s] = __ldcg(&g_hW1[s * F1 + j]);
            float bb = __ldg(&gb1[j]);
#pragma unroll
            for (int i = 0; i < N_NODES; ++i) {
                float a = bb;
#pragma unroll
                for (int s = 0; s < N_NODES; ++s) a += sA[i * N_NODES + s] * hv[s];
                g_x1[i * F1 + j] = fmaxf(a, 0.f);
            }
        }
    } else if (b < 80) {
        int idx = (b - 16) * NT + t;
        if (idx < D3) g_h3[idx] = 0.f;                 // re-zero for next replay
    }
    grid_sync();

    // ======== Phase F: hW2 += x1[15,1024] @ gW2[1024,512] ========
    // 64 blocks, k-chunk 16, 256 j2 threads.  Idle blocks zero hW1.
    if (b < 64) {
        int k0 = b * 16;
        if (t < N_NODES * 16) {
            int i = t >> 4, kk = t & 15;
            sbuf[t] = __ldcg(&g_x1[i * F1 + k0 + kk]);
        }
        __syncthreads();
        if (t < 256) {
            const float2* Wv = reinterpret_cast<const float2*>(gW2);
            float2 acc[N_NODES];
#pragma unroll
            for (int i = 0; i < N_NODES; ++i) { acc[i].x = 0.f; acc[i].y = 0.f; }
#pragma unroll
            for (int kk = 0; kk < 16; ++kk) {
                float2 w = __ldcs(&Wv[((k0 + kk) << 8) + t]);
#pragma unroll
                for (int i = 0; i < N_NODES; ++i) {
                    float h = sbuf[(i << 4) + kk];
                    acc[i].x += h * w.x; acc[i].y += h * w.y;
                }
            }
            int j = t * 2;
#pragma unroll
            for (int i = 0; i < N_NODES; ++i) {
                atomicAdd(&g_hW2[i * F2 + j],     acc[i].x);
                atomicAdd(&g_hW2[i * F2 + j + 1], acc[i].y);
            }
        }
    } else if (b < 85) {
        int idx = (b - 64) * NT + t;
        if (idx < N_NODES * F1) g_hW1[idx] = 0.f;      // re-zero for next replay
    }
    grid_sync();

    // ======== Phase G: x2 = A @ hW2 + gb2 ; mean over nodes  (8 blocks x 64 j) ========
    if (b < 8) {
        if (t < N_NODES * N_NODES) sA[t] = __ldcg(&g_A[t]);
        __syncthreads();
        if (t < 64) {
            int j = b * 64 + t;
            float hv[N_NODES];
#pragma unroll
            for (int s = 0; s < N_NODES; ++s) hv[s] = __ldcg(&g_hW2[s * F2 + j]);
            float bb = __ldg(&gb2[j]);
            float m = 0.f;
#pragma unroll
            for (int i = 0; i < N_NODES; ++i) {
                float a = bb;
#pragma unroll
                for (int s = 0; s < N_NODES; ++s) a += sA[i * N_NODES + s] * hv[s];
                g_x2[i * F2 + j] = a;
                m += a;
            }
            g_mean[j] = m * (1.0f / N_NODES);
        }
    }
    grid_sync();

    // ======== Phase H: ctxpre += mean @ attW  (512 j x 32 k-chunks of 16) ========
    if (g < F2 * 32) {
        int j  = g & 511;
        int k0 = (g >> 9) * 16;
        float s = 0.f;
#pragma unroll
        for (int kk = 0; kk < 16; ++kk)
            s += __ldcg(&g_mean[k0 + kk]) * __ldcs(&attW[(k0 + kk) * F2 + j]);
        atomicAdd(&g_ctxpre[j], s);
    } else if (b >= 22 && b < 32) {
        int idx = (b - 22) * NT + t;
        if (idx < N_NODES * F2) g_hW2[idx] = 0.f;      // re-zero for next replay
    }
    grid_sync();

    // ======== Phase I: tail (block 0 only) ========
    if (b == 0) {
        int w = t >> 5, l = t & 31;
        if (t < F2) {
            sctx[t] = tanhf(__ldcg(&g_ctxpre[t]));
            g_ctxpre[t] = 0.f;                         // re-zero for next replay
        }
        for (int p = t; p < N_NODES * F2; p += NT) sbuf[p] = __ldcg(&g_x2[p]);
        __syncthreads();

        if (w < N_NODES) {
            float p = 0.f;
            for (int j = l; j < F2; j += 32) p += sbuf[w * F2 + j] * sctx[j];
#pragma unroll
            for (int o = 16; o; o >>= 1) p += __shfl_down_sync(0xffffffffu, p, o);
            if (l == 0) sscores[w] = 1.0f / (1.0f + expf(-p));
        }
        __syncthreads();

        if (t < F2) {
            float r = 0.f;
#pragma unroll
            for (int i = 0; i < N_NODES; ++i) r += sbuf[i * F2 + t] * sscores[i];
            srep[t] = r;
        }
        __syncthreads();

        if (w < 3) {
            float p = 0.f;
            for (int j = l; j < F2; j += 32) p += srep[j] * __ldg(&fcW[j * 3 + w]);
#pragma unroll
            for (int o = 16; o; o >>= 1) p += __shfl_down_sync(0xffffffffu, p, o);
            if (l == 0) slog[w] = p + __ldg(&fcb[w]);
        }
        __syncthreads();

        if (t == 0) {
            int cls = 0;
            float tb = __ldg(&target[0]);
            float t1 = __ldg(&target[1]), t2 = __ldg(&target[2]);
            if (t1 > tb) { tb = t1; cls = 1; }
            if (t2 > tb) { tb = t2; cls = 2; }
            float m = fmaxf(slog[0], fmaxf(slog[1], slog[2]));
            float e0 = expf(slog[0] - m), e1 = expf(slog[1] - m), e2 = expf(slog[2] - m);
            float se = e0 + e1 + e2;
            float lse = m + logf(se);
            out[0] = -(slog[cls] - lse);
            out[1] = e0 / se;
            out[2] = e1 / se;
            out[3] = e2 / se;
        }
    }
}

// ---------------- launcher ----------------
extern "C" void kernel_launch(void* const* d_in, const int* in_sizes, int n_in,
                              void* d_out, int out_size) {
    const float* features = (const float*)d_in[0];
    const int*   edges    = (const int*)  d_in[1];
    const float* target   = (const float*)d_in[2];
    const float* W1   = (const float*)d_in[3];
    const float* b1   = (const float*)d_in[4];
    const float* W2   = (const float*)d_in[5];
    const float* b2   = (const float*)d_in[6];
    const float* W3   = (const float*)d_in[7];
    const float* b3   = (const float*)d_in[8];
    const float* gW1  = (const float*)d_in[9];
    const float* gb1  = (const float*)d_in[10];
    const float* gW2  = (const float*)d_in[11];
    const float* gb2  = (const float*)d_in[12];
    const float* attW = (const float*)d_in[13];
    const float* fcW  = (const float*)d_in[14];
    const float* fcb  = (const float*)d_in[15];
    float* out = (float*)d_out;

    fused_gnn<<<NB, NT>>>(features, edges, target, W1, b1, W2, b2, W3, b3,
                          gW1, gb1, gW2, gb2, attW, fcW, fcb, out);
}